// round 2
// baseline (speedup 1.0000x reference)
#include <cuda_runtime.h>
#include <math.h>

#define NB   5000
#define EE   80000
#define ROW1 (4*14*32)      // 1792 floats/node after stage1
#define ROW2 (4*12*64)      // 3072 floats/node after stage2

__device__ float g_T0[(size_t)NB*ROW1];
__device__ float g_Y1[(size_t)NB*ROW1];
__device__ float g_Y2[(size_t)NB*ROW1];
__device__ float g_S [(size_t)NB*ROW1];
__device__ float g_Z [(size_t)NB*ROW2];
__device__ float g_deg[NB];
__device__ int   g_cnt[NB];
__device__ int   g_rowptr[NB+1];
__device__ int   g_cursor[NB];
__device__ int   g_ccol[EE];
__device__ float g_cw[EE];
__device__ float g_w1t[3*48*32];
__device__ float g_w2t[3*96*64];
__device__ float g_wc [3*32*32];

typedef unsigned long long u64;
__device__ __forceinline__ u64 pk(float lo, float hi) {
    u64 r; unsigned a=__float_as_uint(lo), b=__float_as_uint(hi);
    asm("mov.b64 %0, {%1, %2};" : "=l"(r) : "r"(a), "r"(b)); return r;
}
__device__ __forceinline__ void upk(u64 v, float& lo, float& hi) {
    unsigned a,b; asm("mov.b64 {%0, %1}, %2;" : "=r"(a), "=r"(b) : "l"(v));
    lo=__uint_as_float(a); hi=__uint_as_float(b);
}
__device__ __forceinline__ u64 fma2(u64 a, u64 b, u64 c) {
    u64 d; asm("fma.rn.f32x2 %0, %1, %2, %3;" : "=l"(d) : "l"(a), "l"(b), "l"(c)); return d;
}
__device__ __forceinline__ u64 dup2(float x) { return pk(x,x); }
__device__ __forceinline__ float gate(float p, float q, float r) {
    float s = 1.0f/(1.0f+__expf(-q));
    return fmaxf(fmaf(p,s,r), 0.0f);
}

__global__ void k_zero() {
    int i = blockIdx.x*256 + threadIdx.x;
    if (i < NB) { g_cnt[i]=0; g_deg[i]=0.0f; }
}
__global__ void k_hist(const int* __restrict__ ei, const float* __restrict__ ew) {
    int e = blockIdx.x*256 + threadIdx.x;
    if (e < EE) { int r=ei[e]; atomicAdd(&g_cnt[r],1); atomicAdd(&g_deg[r],ew[e]); }
}
__global__ void __launch_bounds__(1024) k_scan() {
    __shared__ int buf[1024]; __shared__ int base;
    int tid = threadIdx.x;
    if (tid==0) base=0;
    __syncthreads();
    for (int ch=0; ch<5; ch++) {
        int idx = ch*1024+tid;
        int v = (idx<NB) ? g_cnt[idx] : 0;
        buf[tid]=v; __syncthreads();
        for (int d=1; d<1024; d<<=1) {
            int t = (tid>=d)?buf[tid-d]:0; __syncthreads();
            buf[tid]+=t; __syncthreads();
        }
        if (idx<NB) { int e=base+buf[tid]-v; g_rowptr[idx]=e; g_cursor[idx]=e; }
        __syncthreads();
        if (tid==1023) base += buf[1023];
        __syncthreads();
    }
    if (tid==0) g_rowptr[NB]=base;
}
__global__ void k_scatter(const int* __restrict__ ei, const float* __restrict__ ew) {
    int e = blockIdx.x*256 + threadIdx.x;
    if (e >= EE) return;
    int r = ei[e], c = ei[EE+e];
    float dgr=g_deg[r], dgc=g_deg[c];
    float dr = dgr>0.0f ? rsqrtf(dgr) : 0.0f;
    float dc = dgc>0.0f ? rsqrtf(dgc) : 0.0f;
    int pos = atomicAdd(&g_cursor[r], 1);
    g_ccol[pos] = c;
    g_cw[pos]   = dr*ew[e]*dc;
}
__global__ void k_prepw(const float* __restrict__ w1, const float* __restrict__ w2,
                        const float* __restrict__ w3,
                        const float* __restrict__ u1, const float* __restrict__ u2,
                        const float* __restrict__ u3,
                        const float* __restrict__ cW) {
    int i = blockIdx.x*256 + threadIdx.x;
    if (i < 4608) {
        int conv=i/1536, r=i%1536, ck=r>>5, o=r&31;
        const float* s = conv==0?w1:(conv==1?w2:w3);
        g_w1t[i] = s[o*48+ck];
    } else if (i < 23040) {
        int i2=i-4608, conv=i2/6144, r=i2%6144, ck=r>>6, o=r&63;
        const float* s = conv==0?u1:(conv==1?u2:u3);
        g_w2t[i2] = s[o*96+ck];
    } else if (i < 26112) {
        // out = T0*(W0-W2) + (Az)*(-W1) + (A^2 z)*(2W2), since Lhat = -A at lmax=2
        int i3=i-23040, j=i3/1024, r=i3%1024;
        float W0=cW[r], W1=cW[1024+r], W2=cW[2048+r];
        g_wc[i3] = (j==0)?(W0-W2):((j==1)?-W1:2.0f*W2);
    }
}

// tc1: X(B,16,N,16) -> T0 node-major (n,b,14,32)
__global__ void __launch_bounds__(224) k_tc1(const float* __restrict__ X,
                                             const float* __restrict__ b1,
                                             const float* __restrict__ b2,
                                             const float* __restrict__ b3) {
    __shared__ float ws[4608];
    __shared__ __align__(16) float xs[1280];   // [b][c][t pad20]
    int n = blockIdx.x, tid = threadIdx.x;
    for (int i=tid; i<4608; i+=224) ws[i]=g_w1t[i];
    for (int i=tid; i<1024; i+=224) {
        int b=i>>8, t=(i>>4)&15, c=i&15;
        xs[b*320+c*20+t] = X[(((b<<4)+t)*5000+n)*16+c];
    }
    __syncthreads();
    int tp = tid>>5, o = tid&31, t0 = tp<<1;   // 7 t-pairs x 32 ch
    u64 aP[4], aQ[4], aR[4];
    u64 i1=dup2(b1[o]), i2=dup2(b2[o]), i3=dup2(b3[o]);
#pragma unroll
    for (int b=0;b<4;b++){aP[b]=i1;aQ[b]=i2;aR[b]=i3;}
    for (int c=0; c<16; c++) {
        u64 w[9];
#pragma unroll
        for (int jk=0; jk<9; jk++)
            w[jk] = dup2(ws[(jk/3)*1536 + (c*3+(jk%3))*32 + o]);
#pragma unroll
        for (int b=0;b<4;b++) {
            const float* xp = &xs[b*320+c*20+t0];
            u64 p0 = *(const u64*)xp;
            u64 p2 = *(const u64*)(xp+2);
            float x0,x1,x2,x3; upk(p0,x0,x1); upk(p2,x2,x3);
            u64 p1 = pk(x1,x2);
            aP[b]=fma2(p0,w[0],aP[b]); aP[b]=fma2(p1,w[1],aP[b]); aP[b]=fma2(p2,w[2],aP[b]);
            aQ[b]=fma2(p0,w[3],aQ[b]); aQ[b]=fma2(p1,w[4],aQ[b]); aQ[b]=fma2(p2,w[5],aQ[b]);
            aR[b]=fma2(p0,w[6],aR[b]); aR[b]=fma2(p1,w[7],aR[b]); aR[b]=fma2(p2,w[8],aR[b]);
        }
    }
#pragma unroll
    for (int b=0;b<4;b++) {
        float pl,ph,ql,qh,rl,rh;
        upk(aP[b],pl,ph); upk(aQ[b],ql,qh); upk(aR[b],rl,rh);
        float* dst = g_T0 + (size_t)n*ROW1 + b*448 + t0*32 + o;
        dst[0]  = gate(pl,ql,rl);
        dst[32] = gate(ph,qh,rh);
    }
}

// SpMV gather per destination node: y = A z  (ROW1/4 = 448 float4 per node)
__global__ void __launch_bounds__(448) k_spmv(int pass) {
    const float* __restrict__ z = pass ? g_Y1 : g_T0;
    float* __restrict__ y       = pass ? g_Y2 : g_Y1;
    int n = blockIdx.x, tid = threadIdx.x;
    int beg = g_rowptr[n], end = g_rowptr[n+1];
    __shared__ int scol[64]; __shared__ float sw[64];
    float4 acc = make_float4(0.f,0.f,0.f,0.f);
    for (int eb=beg; eb<end; eb+=64) {
        int cnt = min(64, end-eb);
        __syncthreads();
        if (tid < cnt) { scol[tid]=g_ccol[eb+tid]; sw[tid]=g_cw[eb+tid]; }
        __syncthreads();
        int j=0;
        for (; j+4<=cnt; j+=4) {
            int c0=scol[j],c1=scol[j+1],c2=scol[j+2],c3=scol[j+3];
            float w0=sw[j],w1=sw[j+1],w2=sw[j+2],w3=sw[j+3];
            float4 v0=((const float4*)(z+(size_t)c0*ROW1))[tid];
            float4 v1=((const float4*)(z+(size_t)c1*ROW1))[tid];
            float4 v2=((const float4*)(z+(size_t)c2*ROW1))[tid];
            float4 v3=((const float4*)(z+(size_t)c3*ROW1))[tid];
            acc.x=fmaf(w0,v0.x,fmaf(w1,v1.x,fmaf(w2,v2.x,fmaf(w3,v3.x,acc.x))));
            acc.y=fmaf(w0,v0.y,fmaf(w1,v1.y,fmaf(w2,v2.y,fmaf(w3,v3.y,acc.y))));
            acc.z=fmaf(w0,v0.z,fmaf(w1,v1.z,fmaf(w2,v2.z,fmaf(w3,v3.z,acc.z))));
            acc.w=fmaf(w0,v0.w,fmaf(w1,v1.w,fmaf(w2,v2.w,fmaf(w3,v3.w,acc.w))));
        }
        for (; j<cnt; j++) {
            int c=scol[j]; float w=sw[j];
            float4 v=((const float4*)(z+(size_t)c*ROW1))[tid];
            acc.x=fmaf(w,v.x,acc.x); acc.y=fmaf(w,v.y,acc.y);
            acc.z=fmaf(w,v.z,acc.z); acc.w=fmaf(w,v.w,acc.w);
        }
    }
    ((float4*)(y+(size_t)n*ROW1))[tid] = acc;
}

// S = relu(T0*Wc0 + Y1*Wc1 + Y2*Wc2 + b)
__global__ void __launch_bounds__(448) k_combine(const float* __restrict__ cb) {
    __shared__ __align__(16) float in_s[3*1920];  // [src][c*60+bt]
    __shared__ float wc_s[3072];
    int n = blockIdx.x, tid = threadIdx.x;
    for (int i=tid; i<3072; i+=448) wc_s[i]=g_wc[i];
    for (int i=tid; i<1792; i+=448) {
        int bt=i>>5, c=i&31, d=c*60+bt;
        size_t gi = (size_t)n*ROW1 + i;
        in_s[d]=g_T0[gi]; in_s[1920+d]=g_Y1[gi]; in_s[3840+d]=g_Y2[gi];
    }
    __syncthreads();
    int q=tid>>5, o=tid&31, bt0=q<<2;   // 14 bt-quads x 32 outs
    u64 a0 = dup2(cb[o]), a1 = a0;
    for (int c=0; c<32; c++) {
        u64 w0=dup2(wc_s[c*32+o]), w1=dup2(wc_s[1024+c*32+o]), w2=dup2(wc_s[2048+c*32+o]);
        int base = c*60+bt0;
        u64 xa0=*(const u64*)&in_s[base],      xa1=*(const u64*)&in_s[base+2];
        u64 xb0=*(const u64*)&in_s[1920+base], xb1=*(const u64*)&in_s[1920+base+2];
        u64 xc0=*(const u64*)&in_s[3840+base], xc1=*(const u64*)&in_s[3840+base+2];
        a0=fma2(xa0,w0,a0); a1=fma2(xa1,w0,a1);
        a0=fma2(xb0,w1,a0); a1=fma2(xb1,w1,a1);
        a0=fma2(xc0,w2,a0); a1=fma2(xc1,w2,a1);
    }
    float h0,h1,h2,h3; upk(a0,h0,h1); upk(a1,h2,h3);
    float* dst = g_S + (size_t)n*ROW1 + bt0*32 + o;
    dst[0]=fmaxf(h0,0.f); dst[32]=fmaxf(h1,0.f);
    dst[64]=fmaxf(h2,0.f); dst[96]=fmaxf(h3,0.f);
}

// tc2: S (n,b,14,32) -> Z (n,b,12,64), 4 nodes per block
__global__ void __launch_bounds__(384) k_tc2(const float* __restrict__ b1,
                                             const float* __restrict__ b2,
                                             const float* __restrict__ b3) {
    extern __shared__ __align__(16) float sm[];
    float* ws = sm;            // 18432
    float* xs = sm + 18432;    // 2560: [b][c][t pad20]
    int tid = threadIdx.x;
    for (int i=tid; i<18432; i+=384) ws[i]=g_w2t[i];
    int tp = tid>>6, o = tid&63, t0 = tp<<1;   // 6 t-pairs x 64 ch
    float bb1=b1[o], bb2=b2[o], bb3=b3[o];
    for (int nn=0; nn<4; nn++) {
        int n = (blockIdx.x<<2) + nn;
        __syncthreads();
        for (int i=tid; i<1792; i+=384) {
            int b=i/448, r=i%448;
            xs[b*640 + (r&31)*20 + (r>>5)] = g_S[(size_t)n*ROW1 + i];
        }
        __syncthreads();
        u64 aP[4], aQ[4], aR[4];
        u64 i1=dup2(bb1), i2=dup2(bb2), i3=dup2(bb3);
#pragma unroll
        for (int b=0;b<4;b++){aP[b]=i1;aQ[b]=i2;aR[b]=i3;}
        for (int c=0; c<32; c++) {
            u64 w[9];
#pragma unroll
            for (int jk=0; jk<9; jk++)
                w[jk] = dup2(ws[(jk/3)*6144 + (c*3+(jk%3))*64 + o]);
#pragma unroll
            for (int b=0;b<4;b++) {
                const float* xp = &xs[b*640+c*20+t0];
                u64 p0 = *(const u64*)xp;
                u64 p2 = *(const u64*)(xp+2);
                float x0,x1,x2,x3; upk(p0,x0,x1); upk(p2,x2,x3);
                u64 p1 = pk(x1,x2);
                aP[b]=fma2(p0,w[0],aP[b]); aP[b]=fma2(p1,w[1],aP[b]); aP[b]=fma2(p2,w[2],aP[b]);
                aQ[b]=fma2(p0,w[3],aQ[b]); aQ[b]=fma2(p1,w[4],aQ[b]); aQ[b]=fma2(p2,w[5],aQ[b]);
                aR[b]=fma2(p0,w[6],aR[b]); aR[b]=fma2(p1,w[7],aR[b]); aR[b]=fma2(p2,w[8],aR[b]);
            }
        }
#pragma unroll
        for (int b=0;b<4;b++) {
            float pl,ph,ql,qh,rl,rh;
            upk(aP[b],pl,ph); upk(aQ[b],ql,qh); upk(aR[b],rl,rh);
            float* dst = g_Z + (size_t)n*ROW2 + b*768 + t0*64 + o;
            dst[0]  = gate(pl,ql,rl);
            dst[64] = gate(ph,qh,rh);
        }
    }
}

// per-node BN over (B,T,C)=3072 vals -> out (B,12,N,64)
__global__ void __launch_bounds__(256) k_bn(const float* __restrict__ gam,
                                            const float* __restrict__ bet,
                                            float* __restrict__ out) {
    __shared__ float red[256];
    int n = blockIdx.x, tid = threadIdx.x;
    const float* zr = g_Z + (size_t)n*ROW2;
    float v[12]; float s = 0.f;
#pragma unroll
    for (int k=0;k<12;k++){ v[k]=zr[tid+(k<<8)]; s+=v[k]; }
    red[tid]=s; __syncthreads();
    for (int st=128; st>0; st>>=1){ if(tid<st) red[tid]+=red[tid+st]; __syncthreads(); }
    float mean = red[0]*(1.f/3072.f);
    __syncthreads();
    float d2=0.f;
#pragma unroll
    for (int k=0;k<12;k++){ float d=v[k]-mean; d2=fmaf(d,d,d2); }
    red[tid]=d2; __syncthreads();
    for (int st=128; st>0; st>>=1){ if(tid<st) red[tid]+=red[tid+st]; __syncthreads(); }
    float var = red[0]*(1.f/3072.f);
    float sc = gam[n]*rsqrtf(var+1e-5f);
    float sh = bet[n]-mean*sc;
#pragma unroll
    for (int k=0;k<12;k++){
        int i = tid+(k<<8), b = i/768, r = i%768;
        out[(((size_t)b*12 + (r>>6))*5000 + n)*64 + (r&63)] = fmaf(v[k], sc, sh);
    }
}

extern "C" void kernel_launch(void* const* d_in, const int* in_sizes, int n_in,
                              void* d_out, int out_size) {
    const float* X   = (const float*)d_in[0];
    const int*   ei  = (const int*)  d_in[1];
    const float* ew  = (const float*)d_in[2];
    const float* w1  = (const float*)d_in[3];
    const float* b1  = (const float*)d_in[4];
    const float* w2  = (const float*)d_in[5];
    const float* b2  = (const float*)d_in[6];
    const float* w3  = (const float*)d_in[7];
    const float* b3  = (const float*)d_in[8];
    const float* cW  = (const float*)d_in[9];
    const float* cb  = (const float*)d_in[10];
    const float* u1  = (const float*)d_in[11];
    const float* ub1 = (const float*)d_in[12];
    const float* u2  = (const float*)d_in[13];
    const float* ub2 = (const float*)d_in[14];
    const float* u3  = (const float*)d_in[15];
    const float* ub3 = (const float*)d_in[16];
    const float* gam = (const float*)d_in[17];
    const float* bet = (const float*)d_in[18];
    float* out = (float*)d_out;

    const int SMEM2 = (18432 + 2560) * 4;
    cudaFuncSetAttribute(k_tc2, cudaFuncAttributeMaxDynamicSharedMemorySize, SMEM2);

    k_zero   <<<(NB+255)/256, 256>>>();
    k_hist   <<<(EE+255)/256, 256>>>(ei, ew);
    k_scan   <<<1, 1024>>>();
    k_scatter<<<(EE+255)/256, 256>>>(ei, ew);
    k_prepw  <<<(26112+255)/256, 256>>>(w1, w2, w3, u1, u2, u3, cW);

    k_tc1    <<<NB, 224>>>(X, b1, b2, b3);
    k_spmv   <<<NB, 448>>>(0);
    k_spmv   <<<NB, 448>>>(1);
    k_combine<<<NB, 448>>>(cb);
    k_tc2    <<<NB/4, 384, SMEM2>>>(ub1, ub2, ub3);
    k_bn     <<<NB, 256>>>(gam, bet, out);
}